// round 9
// baseline (speedup 1.0000x reference)
#include <cuda_runtime.h>
#include <cuda_fp16.h>
#include <cstdint>

// ---------------------------------------------------------------------------
// Plane_refine on sm_100: 2-layer pointwise MLP via fp16 mma.sync (f32 accum)
// + masked max-pool. 296 CTAs x 256 threads (2 CTAs/SM). 128-pt tiles.
// Each warp owns a full 16-point slice across all 128 dims; layer-1 output is
// converted to layer-2 A-fragments IN REGISTERS (acc layout == a-frag layout),
// removing the H1 smem round-trip and inter-layer barriers. N processed in two
// 64-wide halves to bound accumulator registers. H2 stored f16, aliasing A.
// ---------------------------------------------------------------------------

constexpr int N_PTS   = 131072;
constexpr int TILE    = 128;
constexpr int NT      = N_PTS / TILE;     // 1024
constexpr int GRID    = 296;              // 2 per SM
constexpr int THREADS = 256;
constexpr int P       = 64;

// smem. f16 rows: 128 f16 = 256 B, 16B-chunk XOR swizzle chunk' = chunk^(row&7).
constexpr int OFF_W1  = 0;          // 32 KB
constexpr int OFF_W2  = 32768;      // 32 KB
constexpr int OFF_A   = 65536;      // 32 KB: feature f16 (128 rows); later H2 f16
constexpr int OFF_MISC = 98304;
constexpr int OFF_B1   = OFF_MISC + 0;      // f32[128]
constexpr int OFF_B2   = OFF_MISC + 512;    // f32[128]
constexpr int OFF_PL   = OFF_MISC + 1024;   // f32[640]
constexpr int OFF_CTR  = OFF_MISC + 3584;   // f32[4]
constexpr int OFF_PMS  = OFF_MISC + 3600;   // u32[64][4]
constexpr int SMEM_BYTES = OFF_MISC + 4700; // ~103 KB -> 2 CTAs/SM

__device__ __forceinline__ uint32_t smem_u32(const void* p) {
    uint32_t a;
    asm("{ .reg .u64 t; cvta.to.shared.u64 t, %1; cvt.u32.u64 %0, t; }"
        : "=r"(a) : "l"(p));
    return a;
}

__device__ __forceinline__ uint32_t swz(uint32_t region, int row, int kc) {
    return region + (uint32_t)(row * 256) + (uint32_t)((kc ^ (row & 7)) << 4);
}

__device__ __forceinline__ uint32_t pack_h2(float a, float b) {
    __half2 h = __floats2half2_rn(a, b);
    return *(uint32_t*)&h;
}

#define LDSM_X4(r0, r1, r2, r3, a) \
    asm volatile("ldmatrix.sync.aligned.m8n8.x4.shared.b16 {%0,%1,%2,%3}, [%4];" \
                 : "=r"(r0), "=r"(r1), "=r"(r2), "=r"(r3) : "r"(a))
#define MMA16816(d, a0, a1, a2, a3, b0, b1) \
    asm volatile("mma.sync.aligned.m16n8k16.row.col.f32.f16.f16.f32 " \
                 "{%0,%1,%2,%3}, {%4,%5,%6,%7}, {%8,%9}, {%0,%1,%2,%3};" \
                 : "+f"((d)[0]), "+f"((d)[1]), "+f"((d)[2]), "+f"((d)[3]) \
                 : "r"(a0), "r"(a1), "r"(a2), "r"(a3), "r"(b0), "r"(b1))
#define BAR_ARRIVE(id, n) asm volatile("bar.arrive %0, %1;" :: "r"(id), "r"(n) : "memory")
#define BAR_SYNC(id, n)   asm volatile("bar.sync %0, %1;"   :: "r"(id), "r"(n) : "memory")

__global__ void __launch_bounds__(THREADS, 2)
plane_refine_rr(const float* __restrict__ feature, const float* __restrict__ xyz,
                const float* __restrict__ centers,
                const float* __restrict__ plane_center, const float* __restrict__ plane_normal,
                const float* __restrict__ plane_min, const float* __restrict__ plane_max,
                const float* __restrict__ W1, const float* __restrict__ g1,
                const float* __restrict__ b1,
                const float* __restrict__ W2, const float* __restrict__ g2,
                const float* __restrict__ b2,
                float* __restrict__ out)
{
    extern __shared__ char smem[];
    const uint32_t sb = smem_u32(smem);

    float*    b1s = (float*)(smem + OFF_B1);
    float*    b2s = (float*)(smem + OFF_B2);
    float*    pl  = (float*)(smem + OFF_PL);
    float*    ctr = (float*)(smem + OFF_CTR);
    unsigned* pms = (unsigned*)(smem + OFF_PMS);

    const int tid  = threadIdx.x;
    const int lane = tid & 31;
    const int wg   = tid >> 5;      // 0..7: warp owns pts 16wg..16wg+15, planes 8wg..
    const int g    = lane >> 2;
    const int tig  = lane & 3;
    const int s7   = lane & 7;
    const int abit = (lane >> 4) & 1;
    const int bbit = (lane >> 3) & 1;
    const int wrow = (lane & 7) + (((lane >> 4) & 1) << 3);

    // A-fragment base address for this warp (rows 16wg + (lane&15))
    const uint32_t aAddr = sb + OFF_A + (uint32_t)((16 * wg + (lane & 15)) * 256);

    // ---- prologue: weights (fold g, f16, swizzled), consts
    for (int idx = tid; idx < 16384; idx += THREADS) {
        const int o = idx >> 7, k = idx & 127;
        const uint32_t a1 = swz(0, o, k >> 3) + (uint32_t)((k & 7) * 2);
        *(__half*)(smem + a1 + OFF_W1) = __float2half_rn(W1[idx] * g1[o]);
        *(__half*)(smem + a1 + OFF_W2) = __float2half_rn(W2[idx] * g2[o]);
    }
    if (tid < 128) { b1s[tid] = b1[tid]; b2s[tid] = b2[tid]; }
    if (tid < P) {
        const float nx = plane_normal[tid * 3 + 0];
        const float ny = plane_normal[tid * 3 + 1];
        const float nz = plane_normal[tid * 3 + 2];
        pl[tid]       = nx;  pl[64 + tid]  = ny;  pl[128 + tid] = nz;
        pl[192 + tid] = plane_center[tid * 3 + 0] * nx
                      + plane_center[tid * 3 + 1] * ny
                      + plane_center[tid * 3 + 2] * nz;
        pl[256 + tid] = plane_min[tid * 3 + 0];
        pl[320 + tid] = plane_min[tid * 3 + 1];
        pl[384 + tid] = plane_min[tid * 3 + 2];
        pl[448 + tid] = plane_max[tid * 3 + 0];
        pl[512 + tid] = plane_max[tid * 3 + 1];
        pl[576 + tid] = plane_max[tid * 3 + 2];
    }
    if (tid < 3) ctr[tid] = centers[tid];
    __syncthreads();

    const float cx = ctr[0], cy = ctr[1], cz = ctr[2];

    float4 poolv[8];
#pragma unroll
    for (int j = 0; j < 8; j++) poolv[j] = make_float4(0.f, 0.f, 0.f, 0.f);

    for (int t = blockIdx.x; t < NT; t += GRID) {
        const int gbase = t * TILE;

        // ---- load 128-pt feature tile -> f16 A (swizzled)
        {
            const float4* src = (const float4*)(feature + (size_t)gbase * 128);
#pragma unroll
            for (int jj = 0; jj < 16; jj++) {
                const int idx = tid + jj * THREADS;      // 4096 float4
                const int pt  = idx >> 5, k4 = idx & 31;
                const float4 f = src[idx];
                const uint32_t a = swz(OFF_A, pt, k4 >> 1) + (uint32_t)((k4 & 1) * 8);
                *(uint2*)(smem + a) = make_uint2(pack_h2(f.x, f.y), pack_h2(f.z, f.w));
            }
        }

        // ---- masks (warp-private: warp writes & later reads only its 8 planes)
#pragma unroll
        for (int h = 0; h < 4; h++) {
            const int pt = gbase + 32 * h + lane;
            const float px = xyz[(size_t)pt * 3 + 0] + cx;
            const float py = xyz[(size_t)pt * 3 + 1] + cy;
            const float pz = xyz[(size_t)pt * 3 + 2] + cz;
#pragma unroll
            for (int j = 0; j < 8; j++) {
                const int p = 8 * wg + j;
                const float d = fabsf(px * pl[p] + py * pl[64 + p] + pz * pl[128 + p]
                                      - pl[192 + p]);
                bool ok = d < 0.05f;
                float mn, mx;
                mn = pl[256 + p]; mx = pl[448 + p];
                ok = ok && ((px >= mn && px < mx) || (mx == 0.f));
                mn = pl[320 + p]; mx = pl[512 + p];
                ok = ok && ((py >= mn && py < mx) || (mx == 0.f));
                mn = pl[384 + p]; mx = pl[576 + p];
                ok = ok && ((pz >= mn && pz < mx) || (mx == 0.f));
                const unsigned bal = __ballot_sync(0xffffffffu, ok);
                if (lane == 0) pms[p * 4 + h] = bal;
            }
        }
        __syncthreads();   // A ready

        float    acc[8][4];
        uint32_t af[8][4];   // layer-2 A-fragments (f16x2), k-chunks 0..7

        // ================= layer 1: two n-halves, barrier-free =================
#pragma unroll
        for (int H = 0; H < 2; H++) {
#pragma unroll
            for (int jb = 0; jb < 8; jb++)
#pragma unroll
                for (int q = 0; q < 4; q++) acc[jb][q] = 0.f;

            const uint32_t w1b = sb + OFF_W1 + (uint32_t)((64 * H + wrow) * 256);
#pragma unroll
            for (int kk = 0; kk < 8; kk++) {
                const uint32_t kcA = (uint32_t)(((2 * kk + abit) ^ s7) << 4);
                const uint32_t kcB = (uint32_t)(((2 * kk + bbit) ^ s7) << 4);
                uint32_t a[4], b[16];
                LDSM_X4(a[0], a[1], a[2], a[3], aAddr + kcA);
#pragma unroll
                for (int nb = 0; nb < 4; nb++)
                    LDSM_X4(b[4 * nb], b[4 * nb + 1], b[4 * nb + 2], b[4 * nb + 3],
                            w1b + (uint32_t)(nb * 4096) + kcB);
#pragma unroll
                for (int nb = 0; nb < 4; nb++) {
                    MMA16816(acc[2 * nb],     a[0], a[1], a[2], a[3], b[4 * nb],     b[4 * nb + 1]);
                    MMA16816(acc[2 * nb + 1], a[0], a[1], a[2], a[3], b[4 * nb + 2], b[4 * nb + 3]);
                }
            }
            // bias + relu + convert: acc (n-half H) -> a-frags for layer-2 k-chunks 4H..4H+3
#pragma unroll
            for (int jp = 0; jp < 4; jp++) {
                const int jb0 = 2 * jp, jb1 = 2 * jp + 1;
                const int c0 = 64 * H + 8 * jb0 + 2 * tig;
                const int c1 = 64 * H + 8 * jb1 + 2 * tig;
                const float2 bb0 = *(const float2*)&b1s[c0];
                const float2 bb1 = *(const float2*)&b1s[c1];
                af[4 * H + jp][0] = pack_h2(fmaxf(acc[jb0][0] + bb0.x, 0.f),
                                            fmaxf(acc[jb0][1] + bb0.y, 0.f));
                af[4 * H + jp][1] = pack_h2(fmaxf(acc[jb0][2] + bb0.x, 0.f),
                                            fmaxf(acc[jb0][3] + bb0.y, 0.f));
                af[4 * H + jp][2] = pack_h2(fmaxf(acc[jb1][0] + bb1.x, 0.f),
                                            fmaxf(acc[jb1][1] + bb1.y, 0.f));
                af[4 * H + jp][3] = pack_h2(fmaxf(acc[jb1][2] + bb1.x, 0.f),
                                            fmaxf(acc[jb1][3] + bb1.y, 0.f));
            }
        }

        BAR_ARRIVE(1, 2 * THREADS);   // this warp's A-reads (layer 1) are done

        // ================= layer 2 + epilogue: two n-halves ====================
#pragma unroll
        for (int H = 0; H < 2; H++) {
#pragma unroll
            for (int jb = 0; jb < 8; jb++)
#pragma unroll
                for (int q = 0; q < 4; q++) acc[jb][q] = 0.f;

            const uint32_t w2b = sb + OFF_W2 + (uint32_t)((64 * H + wrow) * 256);
#pragma unroll
            for (int kk = 0; kk < 8; kk++) {
                const uint32_t kcB = (uint32_t)(((2 * kk + bbit) ^ s7) << 4);
                uint32_t b[16];
#pragma unroll
                for (int nb = 0; nb < 4; nb++)
                    LDSM_X4(b[4 * nb], b[4 * nb + 1], b[4 * nb + 2], b[4 * nb + 3],
                            w2b + (uint32_t)(nb * 4096) + kcB);
#pragma unroll
                for (int nb = 0; nb < 4; nb++) {
                    MMA16816(acc[2 * nb],     af[kk][0], af[kk][1], af[kk][2], af[kk][3],
                             b[4 * nb], b[4 * nb + 1]);
                    MMA16816(acc[2 * nb + 1], af[kk][0], af[kk][1], af[kk][2], af[kk][3],
                             b[4 * nb + 2], b[4 * nb + 3]);
                }
            }

            if (H == 0) BAR_SYNC(1, 2 * THREADS);  // all warps' layer-1 A-reads done

            // epi2: +b2, relu, f16 into A region (H2)
#pragma unroll
            for (int jb = 0; jb < 8; jb++) {
                const int c0 = 64 * H + 8 * jb + 2 * tig;
                const float2 bb = *(const float2*)&b2s[c0];
                const uint32_t v01 = pack_h2(fmaxf(acc[jb][0] + bb.x, 0.f),
                                             fmaxf(acc[jb][1] + bb.y, 0.f));
                const uint32_t v23 = pack_h2(fmaxf(acc[jb][2] + bb.x, 0.f),
                                             fmaxf(acc[jb][3] + bb.y, 0.f));
                const int r0 = 16 * wg + g;
                *(uint32_t*)(smem + swz(OFF_A, r0,     8 * H + jb) + 4 * tig) = v01;
                *(uint32_t*)(smem + swz(OFF_A, r0 + 8, 8 * H + jb) + 4 * tig) = v23;
            }
        }
        __syncthreads();   // H2 ready everywhere

        // ---- pool: warp's 8 planes over 128 points (f16 H2, f32 max)
#pragma unroll
        for (int j = 0; j < 8; j++) {
            const int p = 8 * wg + j;
#pragma unroll
            for (int h = 0; h < 4; h++) {
                unsigned bits = pms[p * 4 + h];
                while (bits) {
                    const int i = __ffs(bits) - 1;
                    bits &= bits - 1;
                    const int pt = 32 * h + i;
                    // dims 4*lane..4*lane+3: chunk lane>>1, +8B if lane odd
                    const uint2 raw = *(const uint2*)
                        (smem + swz(OFF_A, pt, lane >> 1) + 8 * (lane & 1));
                    const float2 v0 = __half22float2(*(const __half2*)&raw.x);
                    const float2 v1 = __half22float2(*(const __half2*)&raw.y);
                    poolv[j].x = fmaxf(poolv[j].x, v0.x);
                    poolv[j].y = fmaxf(poolv[j].y, v0.y);
                    poolv[j].z = fmaxf(poolv[j].z, v1.x);
                    poolv[j].w = fmaxf(poolv[j].w, v1.y);
                }
            }
        }
        __syncthreads();   // pool done; next tile may overwrite A
    }

    // ---- merge (nonneg float max == uint max on float bits)
    {
        unsigned* o32 = (unsigned*)out;
#pragma unroll
        for (int j = 0; j < 8; j++) {
            const int p = 8 * wg + j;
            const int bidx = p * 128 + lane * 4;
            atomicMax(&o32[bidx + 0], __float_as_uint(poolv[j].x));
            atomicMax(&o32[bidx + 1], __float_as_uint(poolv[j].y));
            atomicMax(&o32[bidx + 2], __float_as_uint(poolv[j].z));
            atomicMax(&o32[bidx + 3], __float_as_uint(poolv[j].w));
        }
    }
}

__global__ void zero_out_kernel(float* __restrict__ out, int n) {
    const int i = blockIdx.x * blockDim.x + threadIdx.x;
    if (i < n) out[i] = 0.f;
}

extern "C" void kernel_launch(void* const* d_in, const int* in_sizes, int n_in,
                              void* d_out, int out_size)
{
    const float* feature      = (const float*)d_in[0];
    const float* xyz          = (const float*)d_in[1];
    const float* centers      = (const float*)d_in[2];
    const float* plane_center = (const float*)d_in[3];
    const float* plane_normal = (const float*)d_in[4];
    const float* plane_min    = (const float*)d_in[5];
    const float* plane_max    = (const float*)d_in[6];
    const float* W1           = (const float*)d_in[7];
    const float* g1           = (const float*)d_in[8];
    const float* b1           = (const float*)d_in[9];
    const float* W2           = (const float*)d_in[10];
    const float* g2           = (const float*)d_in[11];
    const float* b2           = (const float*)d_in[12];
    float* out = (float*)d_out;

    cudaFuncSetAttribute(plane_refine_rr,
                         cudaFuncAttributeMaxDynamicSharedMemorySize, SMEM_BYTES);

    zero_out_kernel<<<(P * 128 + 255) / 256, 256>>>(out, P * 128);
    plane_refine_rr<<<GRID, THREADS, SMEM_BYTES>>>(
        feature, xyz, centers, plane_center, plane_normal, plane_min, plane_max,
        W1, g1, b1, W2, g2, b2, out);
}